// round 3
// baseline (speedup 1.0000x reference)
#include <cuda_runtime.h>
#include <cuda_bf16.h>
#include <cstdint>

typedef unsigned int u32;

#define M_SLOTS 60
#define CHANS   256
#define HW      3136           // 56*56
#define NTOT    802816         // 256*3136 elements per memory slot
#define BATCH   64
#define KPAD    64             // K padded to 64 (rows 60..63 of W are zero)
#define EPS     1e-8f

// Scratch (device globals — no allocation allowed)
__device__ float g_mem_avg[M_SLOTS * CHANS];   // [m][c]
__device__ float g_wbm[BATCH * KPAD];          // [b][k] tf32-rounded weights, k>=60 zero

__device__ __forceinline__ u32 f2tf32(float x) {
    u32 r;
    asm("cvt.rna.tf32.f32 %0, %1;" : "=r"(r) : "f"(x));
    return r;
}

// ---------------- kernel 1: mean over H,W ----------------
// Warp-per-row, shfl-only reduction. Default loads (keep tail of mem in L2 for einsum).
__global__ __launch_bounds__(256) void mean_kernel(const float* __restrict__ mem) {
    const int wrp  = threadIdx.x >> 5;
    const int lane = threadIdx.x & 31;
    const int r = blockIdx.x * 8 + wrp;                       // 0..15359
    const float4* p = (const float4*)(mem + (size_t)r * HW);  // 784 float4 per row
    float s = 0.0f;
#pragma unroll 5
    for (int i = lane; i < 784; i += 32) {
        float4 v = __ldg(p + i);
        s += (v.x + v.y) + (v.z + v.w);
    }
#pragma unroll
    for (int o = 16; o > 0; o >>= 1) s += __shfl_xor_sync(0xffffffffu, s, o);
    if (lane == 0) g_mem_avg[r] = s * (1.0f / (float)HW);
}

// ---------------- kernel 2: cosine sim + softmax -> tf32 weights ----------------
// One block per batch b, 256 threads (8 warps). Writes g_wbm[b][k] (tf32-rounded, padded).
__global__ void weights_kernel(const float* __restrict__ q) {
    const int b = blockIdx.x;
    const int tid = threadIdx.x;
    const int lane = tid & 31;
    const int wrp = tid >> 5;

    __shared__ float s_cos[M_SLOTS];
    __shared__ float s_qn;

    if (wrp == 0) {
        float s = 0.0f;
        const float* qr = q + b * CHANS;
        for (int i = lane; i < CHANS; i += 32) { float v = qr[i]; s += v * v; }
        for (int o = 16; o > 0; o >>= 1) s += __shfl_xor_sync(0xffffffffu, s, o);
        if (lane == 0) s_qn = sqrtf(s);
    }
    __syncthreads();
    const float qn = fmaxf(s_qn, EPS);

    for (int m = wrp; m < M_SLOTS; m += 8) {
        const float* mr = g_mem_avg + m * CHANS;
        const float* qr = q + b * CHANS;
        float dot = 0.0f, mn2 = 0.0f;
        for (int i = lane; i < CHANS; i += 32) {
            float mv = mr[i];
            dot = fmaf(mv, qr[i], dot);
            mn2 = fmaf(mv, mv, mn2);
        }
        for (int o = 16; o > 0; o >>= 1) {
            dot += __shfl_xor_sync(0xffffffffu, dot, o);
            mn2 += __shfl_xor_sync(0xffffffffu, mn2, o);
        }
        if (lane == 0) s_cos[m] = dot / (qn * fmaxf(sqrtf(mn2), EPS));
    }
    __syncthreads();

    if (wrp == 0) {
        float v0 = (lane < M_SLOTS) ? s_cos[lane] : -1e30f;
        float v1 = (lane + 32 < M_SLOTS) ? s_cos[lane + 32] : -1e30f;
        float mx = fmaxf(v0, v1);
        for (int o = 16; o > 0; o >>= 1) mx = fmaxf(mx, __shfl_xor_sync(0xffffffffu, mx, o));
        float e0 = (lane < M_SLOTS) ? expf(v0 - mx) : 0.0f;
        float e1 = (lane + 32 < M_SLOTS) ? expf(v1 - mx) : 0.0f;
        float sm = e0 + e1;
        for (int o = 16; o > 0; o >>= 1) sm += __shfl_xor_sync(0xffffffffu, sm, o);
        float inv = 1.0f / sm;
        // [b][k] layout, tf32-rounded once here
        if (lane < M_SLOTS)
            g_wbm[b * KPAD + lane] = __uint_as_float(f2tf32(e0 * inv));
        if (lane + 32 < M_SLOTS)
            g_wbm[b * KPAD + lane + 32] = __uint_as_float(f2tf32(e1 * inv));
        if (lane < KPAD - M_SLOTS)                    // zero pad k = 60..63
            g_wbm[b * KPAD + M_SLOTS + lane] = 0.0f;
    }
}

// ---------------- kernel 3: einsum via mma.sync tf32 ----------------
// C[64 batch, NTOT spatial] = W[64,64] x Mem[64(=60pad), NTOT]
// Per warp: D tile = 16 batch x 8 spatial (m16n8k8), K-loop kk=0..7.
// Block = 8 warps: (wrp&3)=batch tile, (wrp>>2)=spatial half; covers 16 spatial x 64 batch
// per step; 8 steps => 128 spatial per block. Blocks walk spatial in REVERSE so the
// L2 residue left by mean_kernel (tail of mem) gets reused first.
__global__ __launch_bounds__(256) void einsum_kernel(const float* __restrict__ mem,
                                                     float* __restrict__ out) {
    const int lane = threadIdx.x & 31;
    const int wrp  = threadIdx.x >> 5;
    const int g = lane >> 2;        // group id: 0..7
    const int t = lane & 3;         // thread-in-group: 0..3
    const int b0 = (wrp & 3) * 16;  // batch tile base
    const int nhalf = (wrp >> 2) * 8;

    const size_t n0 = (size_t)(gridDim.x - 1 - blockIdx.x) * 128;

    // Preload A fragments (weights) for all 8 k-groups: 32 regs
    u32 a[8][4];
#pragma unroll
    for (int kk = 0; kk < 8; kk++) {
        const float* wp = g_wbm + (b0 + g) * KPAD + kk * 8 + t;
        a[kk][0] = __float_as_uint(__ldg(wp));
        a[kk][1] = __float_as_uint(__ldg(wp + 8 * KPAD));
        a[kk][2] = __float_as_uint(__ldg(wp + 4));
        a[kk][3] = __float_as_uint(__ldg(wp + 8 * KPAD + 4));
    }

#pragma unroll
    for (int step = 0; step < 8; step++) {
        const size_t n = n0 + step * 16 + nhalf;
        const float* bp = mem + n + g;   // + k*NTOT added per fragment

        float d0 = 0.0f, d1 = 0.0f, d2 = 0.0f, d3 = 0.0f;
#pragma unroll
        for (int kk = 0; kk < 8; kk++) {
            u32 bb0 = f2tf32(__ldg(bp + (size_t)(kk * 8 + t) * NTOT));
            u32 bb1 = 0u;
            if (kk < 7)   // k = 60..63 would be out of bounds; W rows there are zero anyway
                bb1 = f2tf32(__ldg(bp + (size_t)(kk * 8 + t + 4) * NTOT));
            asm volatile(
                "mma.sync.aligned.m16n8k8.row.col.f32.tf32.tf32.f32 "
                "{%0,%1,%2,%3}, {%4,%5,%6,%7}, {%8,%9}, {%0,%1,%2,%3};"
                : "+f"(d0), "+f"(d1), "+f"(d2), "+f"(d3)
                : "r"(a[kk][0]), "r"(a[kk][1]), "r"(a[kk][2]), "r"(a[kk][3]),
                  "r"(bb0), "r"(bb1));
        }

        // D layout: c0/c1 -> (row=g,   col=t*2, t*2+1); c2/c3 -> (row=g+8, same cols)
        float* o0 = out + (size_t)(b0 + g) * NTOT + n + t * 2;
        *(float2*)o0                       = make_float2(d0, d1);
        *(float2*)(o0 + (size_t)8 * NTOT)  = make_float2(d2, d3);
    }
}

// ---------------- launcher ----------------
extern "C" void kernel_launch(void* const* d_in, const int* in_sizes, int n_in,
                              void* d_out, int out_size) {
    const float* mem = (const float*)d_in[0];
    const float* q   = (const float*)d_in[1];
    if (n_in >= 2 && in_sizes[0] < in_sizes[1]) {
        const float* t = mem; mem = q; q = t;
    }
    float* out = (float*)d_out;

    mean_kernel<<<M_SLOTS * CHANS / 8, 256>>>(mem);
    weights_kernel<<<BATCH, 256>>>(q);
    einsum_kernel<<<NTOT / 128, 256>>>(mem, out);
}

// round 5
// speedup vs baseline: 1.4222x; 1.4222x over previous
#include <cuda_runtime.h>
#include <cuda_bf16.h>
#include <cstdint>

typedef unsigned int u32;

#define M_SLOTS 60
#define CHANS   256
#define HW      3136           // 56*56
#define NTOT    802816         // 256*3136 elements per memory slot
#define BATCH   64
#define KPAD    64             // K padded to 64 (rows 60..63 of W are zero)
#define EPS     1e-8f

#define NTILE   128            // spatial floats per block
#define SROW    136            // padded smem row (136 mod 32 = 8 -> conflict-free B-frags)

// Scratch (device globals — no allocation allowed)
__device__ float g_mem_avg[M_SLOTS * CHANS];   // [m][c]
__device__ float g_wbm[BATCH * KPAD];          // [b][k] tf32-rounded weights, k>=60 zero
// Pre-swizzled A fragments: [mpair(2)][lane(32)][mi(2)][kk(8)][r(4)]
__device__ float g_wA[2 * 32 * 2 * 8 * 4];

__device__ __forceinline__ u32 f2tf32(float x) {
    u32 r;
    asm("cvt.rna.tf32.f32 %0, %1;" : "=r"(r) : "f"(x));
    return r;
}

// ---------------- kernel 1: mean over H,W ----------------
__global__ __launch_bounds__(256) void mean_kernel(const float* __restrict__ mem) {
    const int wrp  = threadIdx.x >> 5;
    const int lane = threadIdx.x & 31;
    const int r = blockIdx.x * 8 + wrp;                       // 0..15359
    const float4* p = (const float4*)(mem + (size_t)r * HW);  // 784 float4 per row
    float s = 0.0f;
#pragma unroll 5
    for (int i = lane; i < 784; i += 32) {
        float4 v = __ldg(p + i);
        s += (v.x + v.y) + (v.z + v.w);
    }
#pragma unroll
    for (int o = 16; o > 0; o >>= 1) s += __shfl_xor_sync(0xffffffffu, s, o);
    if (lane == 0) g_mem_avg[r] = s * (1.0f / (float)HW);
}

// ---------------- kernel 2: cosine sim + softmax -> tf32 weights ----------------
__global__ void weights_kernel(const float* __restrict__ q) {
    const int b = blockIdx.x;
    const int tid = threadIdx.x;
    const int lane = tid & 31;
    const int wrp = tid >> 5;

    __shared__ float s_cos[M_SLOTS];
    __shared__ float s_qn;

    if (wrp == 0) {
        float s = 0.0f;
        const float* qr = q + b * CHANS;
        for (int i = lane; i < CHANS; i += 32) { float v = qr[i]; s += v * v; }
        for (int o = 16; o > 0; o >>= 1) s += __shfl_xor_sync(0xffffffffu, s, o);
        if (lane == 0) s_qn = sqrtf(s);
    }
    __syncthreads();
    const float qn = fmaxf(s_qn, EPS);

    for (int m = wrp; m < M_SLOTS; m += 8) {
        const float* mr = g_mem_avg + m * CHANS;
        const float* qr = q + b * CHANS;
        float dot = 0.0f, mn2 = 0.0f;
        for (int i = lane; i < CHANS; i += 32) {
            float mv = mr[i];
            dot = fmaf(mv, qr[i], dot);
            mn2 = fmaf(mv, mv, mn2);
        }
        for (int o = 16; o > 0; o >>= 1) {
            dot += __shfl_xor_sync(0xffffffffu, dot, o);
            mn2 += __shfl_xor_sync(0xffffffffu, mn2, o);
        }
        if (lane == 0) s_cos[m] = dot / (qn * fmaxf(sqrtf(mn2), EPS));
    }
    __syncthreads();

    if (wrp == 0) {
        float v0 = (lane < M_SLOTS) ? s_cos[lane] : -1e30f;
        float v1 = (lane + 32 < M_SLOTS) ? s_cos[lane + 32] : -1e30f;
        float mx = fmaxf(v0, v1);
        for (int o = 16; o > 0; o >>= 1) mx = fmaxf(mx, __shfl_xor_sync(0xffffffffu, mx, o));
        float e0 = (lane < M_SLOTS) ? expf(v0 - mx) : 0.0f;
        float e1 = (lane + 32 < M_SLOTS) ? expf(v1 - mx) : 0.0f;
        float sm = e0 + e1;
        for (int o = 16; o > 0; o >>= 1) sm += __shfl_xor_sync(0xffffffffu, sm, o);
        float inv = 1.0f / sm;
        if (lane < M_SLOTS)
            g_wbm[b * KPAD + lane] = __uint_as_float(f2tf32(e0 * inv));
        if (lane + 32 < M_SLOTS)
            g_wbm[b * KPAD + lane + 32] = __uint_as_float(f2tf32(e1 * inv));
        if (lane < KPAD - M_SLOTS)                    // zero pad k = 60..63
            g_wbm[b * KPAD + M_SLOTS + lane] = 0.0f;
    }
}

// ---------------- kernel 2b: pack A fragments ----------------
// g_wA[mpair][lane][mi][kk][r]; thread-contiguous 64-float chunks => 16 LDG.128 in einsum.
__global__ void pack_kernel() {
    const int tid = threadIdx.x;
    if (tid >= 256) return;
    const int mpair = tid >> 7;            // 0..1
    const int lane  = (tid >> 2) & 31;     // 0..31
    const int mi    = (tid >> 1) & 1;      // 0..1
    const int kh    = tid & 1;             // kk half: 0..1
    const int g = lane >> 2, t = lane & 3;
    const int m0 = mpair * 32 + mi * 16;
    float* dst = g_wA + (((mpair * 32 + lane) * 2 + mi) * 8) * 4;
    for (int kk = kh * 4; kk < kh * 4 + 4; kk++) {
        dst[kk * 4 + 0] = g_wbm[(m0 + g)     * KPAD + kk * 8 + t];
        dst[kk * 4 + 1] = g_wbm[(m0 + g + 8) * KPAD + kk * 8 + t];
        dst[kk * 4 + 2] = g_wbm[(m0 + g)     * KPAD + kk * 8 + t + 4];
        dst[kk * 4 + 3] = g_wbm[(m0 + g + 8) * KPAD + kk * 8 + t + 4];
    }
}

// ---------------- kernel 3: einsum via smem-staged tf32 MMA ----------------
// Block: 256 thr, one spatial tile of 128 floats, all 64 batches.
// Stage tile[64][136] (rows 60..63 zero, tf32-rounded during staging).
// Warp (8 total) = (mpair = wrp&1) x (nquad = wrp>>1): 2 m-tiles x 4 n-tiles x 8 k.
__global__ __launch_bounds__(256, 2) void einsum_kernel(const float* __restrict__ mem,
                                                        float* __restrict__ out) {
    __shared__ float tile[64 * SROW];   // ~34.8 KB

    const int tid  = threadIdx.x;
    const int lane = tid & 31;
    const int wrp  = tid >> 5;
    // reversed order: harvest mean_kernel's L2 tail residue
    const size_t n0 = (size_t)(gridDim.x - 1 - blockIdx.x) * NTILE;

    // ---- stage: 64 rows x 32 float4 ----
#pragma unroll
    for (int it = 0; it < 8; it++) {
        int j = tid + it * 256;            // 0..2047
        int row = j >> 5, c4 = j & 31;
        float4 v = make_float4(0.f, 0.f, 0.f, 0.f);
        if (row < M_SLOTS)
            v = __ldg((const float4*)(mem + (size_t)row * NTOT + n0 + c4 * 4));
        v.x = __uint_as_float(f2tf32(v.x));
        v.y = __uint_as_float(f2tf32(v.y));
        v.z = __uint_as_float(f2tf32(v.z));
        v.w = __uint_as_float(f2tf32(v.w));
        *(float4*)(tile + row * SROW + c4 * 4) = v;
    }

    // ---- A fragments: 16 LDG.128 from pre-swizzled layout ----
    const int mpair = wrp & 1;
    const int nquad = wrp >> 1;            // 0..3 -> n-tiles 4*nquad .. 4*nquad+3
    u32 a[2][8][4];
    {
        const float4* ap = (const float4*)(g_wA + (mpair * 32 + lane) * 64);
#pragma unroll
        for (int mi = 0; mi < 2; mi++)
#pragma unroll
            for (int kk = 0; kk < 8; kk++) {
                float4 v = __ldg(ap + mi * 8 + kk);
                a[mi][kk][0] = __float_as_uint(v.x);
                a[mi][kk][1] = __float_as_uint(v.y);
                a[mi][kk][2] = __float_as_uint(v.z);
                a[mi][kk][3] = __float_as_uint(v.w);
            }
    }
    __syncthreads();

    const int g = lane >> 2, t = lane & 3;
    float c[2][4][4];
#pragma unroll
    for (int mi = 0; mi < 2; mi++)
#pragma unroll
        for (int nt = 0; nt < 4; nt++)
#pragma unroll
            for (int r = 0; r < 4; r++) c[mi][nt][r] = 0.0f;

#pragma unroll
    for (int kk = 0; kk < 8; kk++) {
        const float* r0 = tile + (kk * 8 + t) * SROW + nquad * 32 + g;
        const float* r1 = r0 + 4 * SROW;
        u32 b0[4], b1[4];
#pragma unroll
        for (int nt = 0; nt < 4; nt++) {
            b0[nt] = __float_as_uint(r0[nt * 8]);
            b1[nt] = __float_as_uint(r1[nt * 8]);
        }
#pragma unroll
        for (int mi = 0; mi < 2; mi++)
#pragma unroll
            for (int nt = 0; nt < 4; nt++) {
                asm volatile(
                    "mma.sync.aligned.m16n8k8.row.col.f32.tf32.tf32.f32 "
                    "{%0,%1,%2,%3}, {%4,%5,%6,%7}, {%8,%9}, {%0,%1,%2,%3};"
                    : "+f"(c[mi][nt][0]), "+f"(c[mi][nt][1]),
                      "+f"(c[mi][nt][2]), "+f"(c[mi][nt][3])
                    : "r"(a[mi][kk][0]), "r"(a[mi][kk][1]),
                      "r"(a[mi][kk][2]), "r"(a[mi][kk][3]),
                      "r"(b0[nt]), "r"(b1[nt]));
            }
    }

    // ---- epilogue: c0/c1 -> (row g, cols 2t,2t+1), c2/c3 -> row g+8 ----
#pragma unroll
    for (int mi = 0; mi < 2; mi++) {
        const int brow = mpair * 32 + mi * 16 + g;
#pragma unroll
        for (int nt = 0; nt < 4; nt++) {
            float* o0 = out + (size_t)brow * NTOT + n0 + nquad * 32 + nt * 8 + t * 2;
            *(float2*)o0                      = make_float2(c[mi][nt][0], c[mi][nt][1]);
            *(float2*)(o0 + (size_t)8 * NTOT) = make_float2(c[mi][nt][2], c[mi][nt][3]);
        }
    }
}

// ---------------- launcher ----------------
extern "C" void kernel_launch(void* const* d_in, const int* in_sizes, int n_in,
                              void* d_out, int out_size) {
    const float* mem = (const float*)d_in[0];
    const float* q   = (const float*)d_in[1];
    if (n_in >= 2 && in_sizes[0] < in_sizes[1]) {
        const float* t = mem; mem = q; q = t;
    }
    float* out = (float*)d_out;

    mean_kernel<<<M_SLOTS * CHANS / 8, 256>>>(mem);
    weights_kernel<<<BATCH, 256>>>(q);
    pack_kernel<<<1, 256>>>();
    einsum_kernel<<<NTOT / NTILE, 256>>>(mem, out);
}

// round 6
// speedup vs baseline: 2.0081x; 1.4120x over previous
#include <cuda_runtime.h>
#include <cuda_bf16.h>
#include <cstdint>

typedef unsigned int u32;

#define M_SLOTS 60
#define CHANS   256
#define HW      3136           // 56*56
#define NTOT    802816         // 256*3136 elements per memory slot
#define BATCH   64
#define KPAD    64             // K padded to 64 (rows 60..63 of W are zero)
#define EPS     1e-8f

#define NTILE   64             // spatial floats per tile
#define SROW    72             // padded smem row (72 mod 32 = 8 -> conflict-free B-frags)
#define BUFN    (64 * SROW)    // floats per stage buffer
#define NT      (NTOT / NTILE) // 12544 tiles
#define GRID    444            // 148 SMs * 3 CTAs

// Scratch (device globals — no allocation allowed)
__device__ float g_mem_avg[M_SLOTS * CHANS];   // [m][c]
__device__ float g_wbm[BATCH * KPAD];          // [b][k] tf32-rounded weights, k>=60 zero
// A fragments, warp-coalesced: [mtile(4)][kk(8)][lane(32)][r(4)]
__device__ float g_wA[4 * 8 * 32 * 4];

__device__ __forceinline__ u32 f2tf32(float x) {
    u32 r;
    asm("cvt.rna.tf32.f32 %0, %1;" : "=r"(r) : "f"(x));
    return r;
}

// ---------------- kernel 1: mean over H,W ----------------
__global__ __launch_bounds__(256) void mean_kernel(const float* __restrict__ mem) {
    const int wrp  = threadIdx.x >> 5;
    const int lane = threadIdx.x & 31;
    const int r = blockIdx.x * 8 + wrp;                       // 0..15359
    const float4* p = (const float4*)(mem + (size_t)r * HW);  // 784 float4 per row
    float s = 0.0f;
#pragma unroll 5
    for (int i = lane; i < 784; i += 32) {
        float4 v = __ldg(p + i);
        s += (v.x + v.y) + (v.z + v.w);
    }
#pragma unroll
    for (int o = 16; o > 0; o >>= 1) s += __shfl_xor_sync(0xffffffffu, s, o);
    if (lane == 0) g_mem_avg[r] = s * (1.0f / (float)HW);
}

// ---------------- kernel 2: cosine sim + softmax -> tf32 weights ----------------
__global__ void weights_kernel(const float* __restrict__ q) {
    const int b = blockIdx.x;
    const int tid = threadIdx.x;
    const int lane = tid & 31;
    const int wrp = tid >> 5;

    __shared__ float s_cos[M_SLOTS];
    __shared__ float s_qn;

    if (wrp == 0) {
        float s = 0.0f;
        const float* qr = q + b * CHANS;
        for (int i = lane; i < CHANS; i += 32) { float v = qr[i]; s += v * v; }
        for (int o = 16; o > 0; o >>= 1) s += __shfl_xor_sync(0xffffffffu, s, o);
        if (lane == 0) s_qn = sqrtf(s);
    }
    __syncthreads();
    const float qn = fmaxf(s_qn, EPS);

    for (int m = wrp; m < M_SLOTS; m += 8) {
        const float* mr = g_mem_avg + m * CHANS;
        const float* qr = q + b * CHANS;
        float dot = 0.0f, mn2 = 0.0f;
        for (int i = lane; i < CHANS; i += 32) {
            float mv = mr[i];
            dot = fmaf(mv, qr[i], dot);
            mn2 = fmaf(mv, mv, mn2);
        }
        for (int o = 16; o > 0; o >>= 1) {
            dot += __shfl_xor_sync(0xffffffffu, dot, o);
            mn2 += __shfl_xor_sync(0xffffffffu, mn2, o);
        }
        if (lane == 0) s_cos[m] = dot / (qn * fmaxf(sqrtf(mn2), EPS));
    }
    __syncthreads();

    if (wrp == 0) {
        float v0 = (lane < M_SLOTS) ? s_cos[lane] : -1e30f;
        float v1 = (lane + 32 < M_SLOTS) ? s_cos[lane + 32] : -1e30f;
        float mx = fmaxf(v0, v1);
        for (int o = 16; o > 0; o >>= 1) mx = fmaxf(mx, __shfl_xor_sync(0xffffffffu, mx, o));
        float e0 = (lane < M_SLOTS) ? expf(v0 - mx) : 0.0f;
        float e1 = (lane + 32 < M_SLOTS) ? expf(v1 - mx) : 0.0f;
        float sm = e0 + e1;
        for (int o = 16; o > 0; o >>= 1) sm += __shfl_xor_sync(0xffffffffu, sm, o);
        float inv = 1.0f / sm;
        if (lane < M_SLOTS)
            g_wbm[b * KPAD + lane] = __uint_as_float(f2tf32(e0 * inv));
        if (lane + 32 < M_SLOTS)
            g_wbm[b * KPAD + lane + 32] = __uint_as_float(f2tf32(e1 * inv));
        if (lane < KPAD - M_SLOTS)                    // zero pad k = 60..63
            g_wbm[b * KPAD + M_SLOTS + lane] = 0.0f;
    }
}

// ---------------- kernel 2b: pack A fragments ----------------
// g_wA[mtile][kk][lane][r]: warp reading (kk fixed, lane varying) is fully coalesced.
__global__ void pack_kernel() {
    const int tid = threadIdx.x;
#pragma unroll
    for (int i = 0; i < 4; i++) {
        int slot = tid + i * 256;              // 0..1023 -> (mtile, kk, lane)
        int mtile = slot >> 8;
        int kk    = (slot >> 5) & 7;
        int lane  = slot & 31;
        int g = lane >> 2, t = lane & 3;
        int m0 = mtile * 16;
        int k  = kk * 8 + t;
        float4 v;
        v.x = g_wbm[(m0 + g)     * KPAD + k];
        v.y = g_wbm[(m0 + g + 8) * KPAD + k];
        v.z = g_wbm[(m0 + g)     * KPAD + k + 4];
        v.w = g_wbm[(m0 + g + 8) * KPAD + k + 4];
        *(float4*)(g_wA + (size_t)slot * 4) = v;
    }
}

// ---------------- kernel 3: einsum, cp.async double-buffered tf32 MMA ----------------
// Persistent strips: 444 blocks, each handles ~28 consecutive 64-float tiles.
// Per tile: stage mem[60][64] via cp.async.cg (rows 60..63 pre-zeroed), then
// 8 warps = (mtile 0..3) x (nhalf 0..1): 8 kk x 4 nt MMAs each.
__global__ __launch_bounds__(256, 3) void einsum_kernel(const float* __restrict__ mem,
                                                        float* __restrict__ out) {
    __shared__ float buf[2][BUFN];   // 36,864 B

    const int tid  = threadIdx.x;
    const int lane = tid & 31;
    const int wrp  = tid >> 5;
    const int mtile = wrp & 3;
    const int nhalf = wrp >> 2;
    const int g = lane >> 2, t = lane & 3;

    const int qq = NT / GRID, rr = NT % GRID;          // 28, 112
    const int bid = blockIdx.x;
    const int len  = qq + (bid < rr ? 1 : 0);
    const int base = bid * qq + (bid < rr ? bid : rr);

    const u32 sbase = (u32)__cvta_generic_to_shared(&buf[0][0]);

    // zero rows 60..63 of both buffers (never written by cp.async)
    for (int j = tid; j < 2 * 4 * SROW; j += 256) {
        int bfi = j / (4 * SROW);
        int rem = j % (4 * SROW);
        buf[bfi][(60 + rem / SROW) * SROW + (rem % SROW)] = 0.0f;
    }

    // stage loader: 60 rows x 16 chunks of 16B = 960 chunks
    auto load_tile = [&](int tix, int bsel) {
        const size_t n0 = (size_t)(base + tix) * NTILE;
#pragma unroll
        for (int i = 0; i < 4; i++) {
            int j = tid + i * 256;
            if (j < 960) {
                int row = j >> 4, c = (j & 15) << 2;
                u32 dst = sbase + (u32)((bsel * BUFN + row * SROW + c) * 4);
                const float* src = mem + (size_t)row * NTOT + n0 + c;
                asm volatile("cp.async.cg.shared.global [%0], [%1], 16;\n"
                             :: "r"(dst), "l"(src));
            }
        }
    };

    if (len > 0) load_tile(0, 0);
    asm volatile("cp.async.commit_group;\n" ::: "memory");

    const float4* ap = (const float4*)g_wA + (mtile * 8) * 32 + lane;

    for (int tix = 0; tix < len; tix++) {
        if (tix + 1 < len) load_tile(tix + 1, (tix + 1) & 1);
        asm volatile("cp.async.commit_group;\n" ::: "memory");
        asm volatile("cp.async.wait_group 1;\n" ::: "memory");
        __syncthreads();

        const float* tp = buf[tix & 1];
        const size_t n0 = (size_t)(base + tix) * NTILE;

        float c[4][4];
#pragma unroll
        for (int nt = 0; nt < 4; nt++)
#pragma unroll
            for (int r = 0; r < 4; r++) c[nt][r] = 0.0f;

#pragma unroll
        for (int kk = 0; kk < 8; kk++) {
            float4 av = __ldg(ap + kk * 32);
            u32 a0 = __float_as_uint(av.x), a1 = __float_as_uint(av.y);
            u32 a2 = __float_as_uint(av.z), a3 = __float_as_uint(av.w);
            const float* r0 = tp + (kk * 8 + t) * SROW + nhalf * 32 + g;
            const float* r1 = r0 + 4 * SROW;
#pragma unroll
            for (int nt = 0; nt < 4; nt++) {
                u32 b0 = f2tf32(r0[nt * 8]);
                u32 b1 = f2tf32(r1[nt * 8]);
                asm volatile(
                    "mma.sync.aligned.m16n8k8.row.col.f32.tf32.tf32.f32 "
                    "{%0,%1,%2,%3}, {%4,%5,%6,%7}, {%8,%9}, {%0,%1,%2,%3};"
                    : "+f"(c[nt][0]), "+f"(c[nt][1]), "+f"(c[nt][2]), "+f"(c[nt][3])
                    : "r"(a0), "r"(a1), "r"(a2), "r"(a3), "r"(b0), "r"(b1));
            }
        }

        // epilogue: c0/c1 -> (row m0+g, cols 2t,2t+1), c2/c3 -> row m0+g+8
        const int brow = mtile * 16 + g;
        float* o0 = out + (size_t)brow * NTOT + n0 + nhalf * 32 + t * 2;
#pragma unroll
        for (int nt = 0; nt < 4; nt++) {
            *(float2*)(o0 + nt * 8)                      = make_float2(c[nt][0], c[nt][1]);
            *(float2*)(o0 + nt * 8 + (size_t)8 * NTOT)   = make_float2(c[nt][2], c[nt][3]);
        }
        __syncthreads();   // protect buf[tix&1] before it's refilled next iteration
    }
}

// ---------------- launcher ----------------
extern "C" void kernel_launch(void* const* d_in, const int* in_sizes, int n_in,
                              void* d_out, int out_size) {
    const float* mem = (const float*)d_in[0];
    const float* q   = (const float*)d_in[1];
    if (n_in >= 2 && in_sizes[0] < in_sizes[1]) {
        const float* t = mem; mem = q; q = t;
    }
    float* out = (float*)d_out;

    mean_kernel<<<M_SLOTS * CHANS / 8, 256>>>(mem);
    weights_kernel<<<BATCH, 256>>>(q);
    pack_kernel<<<1, 256>>>();
    einsum_kernel<<<GRID, 256>>>(mem, out);
}

// round 7
// speedup vs baseline: 2.0338x; 1.0128x over previous
#include <cuda_runtime.h>
#include <cuda_bf16.h>
#include <cstdint>

typedef unsigned int u32;

#define M_SLOTS 60
#define CHANS   256
#define HW      3136           // 56*56
#define NTOT    802816         // 256*3136 elements per memory slot
#define BATCH   64
#define KPAD    64             // K padded to 64 (rows 60..63 of W are zero)
#define EPS     1e-8f

#define NTILE   64             // spatial floats per tile
#define SROW    72             // padded stage row (72 mod 32 = 8 -> conflict-free B-frags)
#define STAGEN  (64 * SROW)    // 4608 floats per stage buffer
#define NSTAGE  3
#define OROW    68             // output transpose buffer row pad
#define OBUFN   (64 * OROW)    // 4352 floats
#define SMEM_BYTES ((NSTAGE * STAGEN + OBUFN) * 4)   // 72704 B
#define NT      (NTOT / NTILE) // 12544 tiles
#define GRID    444            // 148 SMs * 3 CTAs

// Scratch (device globals — no allocation allowed)
__device__ float g_mem_avg[M_SLOTS * CHANS];   // [m][c]
__device__ float g_wbm[BATCH * KPAD];          // [b][k] tf32-rounded weights, k>=60 zero
// A fragments, warp-coalesced: [mtile(4)][kk(8)][lane(32)][r(4)]
__device__ float g_wA[4 * 8 * 32 * 4];

__device__ __forceinline__ u32 f2tf32(float x) {
    u32 r;
    asm("cvt.rna.tf32.f32 %0, %1;" : "=r"(r) : "f"(x));
    return r;
}

// ---------------- kernel 1: mean over H,W ----------------
__global__ __launch_bounds__(256) void mean_kernel(const float* __restrict__ mem) {
    const int wrp  = threadIdx.x >> 5;
    const int lane = threadIdx.x & 31;
    const int r = blockIdx.x * 8 + wrp;                       // 0..15359
    const float4* p = (const float4*)(mem + (size_t)r * HW);  // 784 float4 per row
    float s = 0.0f;
#pragma unroll 5
    for (int i = lane; i < 784; i += 32) {
        float4 v = __ldg(p + i);
        s += (v.x + v.y) + (v.z + v.w);
    }
#pragma unroll
    for (int o = 16; o > 0; o >>= 1) s += __shfl_xor_sync(0xffffffffu, s, o);
    if (lane == 0) g_mem_avg[r] = s * (1.0f / (float)HW);
}

// ---------------- kernel 2: cosine sim + softmax -> tf32 weights ----------------
__global__ void weights_kernel(const float* __restrict__ q) {
    const int b = blockIdx.x;
    const int tid = threadIdx.x;
    const int lane = tid & 31;
    const int wrp = tid >> 5;

    __shared__ float s_cos[M_SLOTS];
    __shared__ float s_qn;

    if (wrp == 0) {
        float s = 0.0f;
        const float* qr = q + b * CHANS;
        for (int i = lane; i < CHANS; i += 32) { float v = qr[i]; s += v * v; }
        for (int o = 16; o > 0; o >>= 1) s += __shfl_xor_sync(0xffffffffu, s, o);
        if (lane == 0) s_qn = sqrtf(s);
    }
    __syncthreads();
    const float qn = fmaxf(s_qn, EPS);

    for (int m = wrp; m < M_SLOTS; m += 8) {
        const float* mr = g_mem_avg + m * CHANS;
        const float* qr = q + b * CHANS;
        float dot = 0.0f, mn2 = 0.0f;
        for (int i = lane; i < CHANS; i += 32) {
            float mv = mr[i];
            dot = fmaf(mv, qr[i], dot);
            mn2 = fmaf(mv, mv, mn2);
        }
        for (int o = 16; o > 0; o >>= 1) {
            dot += __shfl_xor_sync(0xffffffffu, dot, o);
            mn2 += __shfl_xor_sync(0xffffffffu, mn2, o);
        }
        if (lane == 0) s_cos[m] = dot / (qn * fmaxf(sqrtf(mn2), EPS));
    }
    __syncthreads();

    if (wrp == 0) {
        float v0 = (lane < M_SLOTS) ? s_cos[lane] : -1e30f;
        float v1 = (lane + 32 < M_SLOTS) ? s_cos[lane + 32] : -1e30f;
        float mx = fmaxf(v0, v1);
        for (int o = 16; o > 0; o >>= 1) mx = fmaxf(mx, __shfl_xor_sync(0xffffffffu, mx, o));
        float e0 = (lane < M_SLOTS) ? expf(v0 - mx) : 0.0f;
        float e1 = (lane + 32 < M_SLOTS) ? expf(v1 - mx) : 0.0f;
        float sm = e0 + e1;
        for (int o = 16; o > 0; o >>= 1) sm += __shfl_xor_sync(0xffffffffu, sm, o);
        float inv = 1.0f / sm;
        if (lane < M_SLOTS)
            g_wbm[b * KPAD + lane] = __uint_as_float(f2tf32(e0 * inv));
        if (lane + 32 < M_SLOTS)
            g_wbm[b * KPAD + lane + 32] = __uint_as_float(f2tf32(e1 * inv));
        if (lane < KPAD - M_SLOTS)                    // zero pad k = 60..63
            g_wbm[b * KPAD + M_SLOTS + lane] = 0.0f;
    }
}

// ---------------- kernel 2b: pack A fragments ----------------
// g_wA[mtile][kk][lane][r]: warp reading (kk fixed, lane varying) is fully coalesced.
__global__ void pack_kernel() {
    const int tid = threadIdx.x;
#pragma unroll
    for (int i = 0; i < 4; i++) {
        int slot = tid + i * 256;              // 0..1023 -> (mtile, kk, lane)
        int mtile = slot >> 8;
        int kk    = (slot >> 5) & 7;
        int lane  = slot & 31;
        int g = lane >> 2, t = lane & 3;
        int m0 = mtile * 16;
        int k  = kk * 8 + t;
        float4 v;
        v.x = g_wbm[(m0 + g)     * KPAD + k];
        v.y = g_wbm[(m0 + g + 8) * KPAD + k];
        v.z = g_wbm[(m0 + g)     * KPAD + k + 4];
        v.w = g_wbm[(m0 + g + 8) * KPAD + k + 4];
        *(float4*)(g_wA + (size_t)slot * 4) = v;
    }
}

// ---------------- kernel 3: einsum, 3-stage cp.async ring + transposed epilogue ----------------
__global__ __launch_bounds__(256, 3) void einsum_kernel(const float* __restrict__ mem,
                                                        float* __restrict__ out) {
    extern __shared__ float smem[];
    float* stage = smem;                    // NSTAGE * STAGEN
    float* obuf  = smem + NSTAGE * STAGEN;  // OBUFN

    const int tid  = threadIdx.x;
    const int lane = tid & 31;
    const int wrp  = tid >> 5;
    const int mtile = wrp & 3;
    const int nhalf = wrp >> 2;
    const int g = lane >> 2, t = lane & 3;

    const int qq = NT / GRID, rr = NT % GRID;          // 28, 112
    const int bid = blockIdx.x;
    const int len  = qq + (bid < rr ? 1 : 0);
    const int base = bid * qq + (bid < rr ? bid : rr);

    const u32 sbase = (u32)__cvta_generic_to_shared(smem);

    // zero k-pad rows 60..63 of all stage buffers (cp.async never writes them)
    for (int j = tid; j < NSTAGE * 4 * SROW; j += 256) {
        int s = j / (4 * SROW);
        int rem = j % (4 * SROW);
        stage[s * STAGEN + (60 + rem / SROW) * SROW + (rem % SROW)] = 0.0f;
    }

    // stage loader: 60 rows x 16 chunks of 16B = 960 chunks
    auto load_tile = [&](int tix, int bsel) {
#pragma unroll
        for (int i = 0; i < 4; i++) {
            int j = tid + i * 256;
            if (j < 960) {
                int row = j >> 4, c = (j & 15) << 2;
                u32 dst = sbase + (u32)((bsel * STAGEN + row * SROW + c) * 4);
                const float* src = mem + (size_t)row * NTOT + (size_t)(base + tix) * NTILE + c;
                asm volatile("cp.async.cg.shared.global [%0], [%1], 16;\n"
                             :: "r"(dst), "l"(src));
            }
        }
    };

    if (0 < len) load_tile(0, 0);
    asm volatile("cp.async.commit_group;\n" ::: "memory");
    if (1 < len) load_tile(1, 1);
    asm volatile("cp.async.commit_group;\n" ::: "memory");

    const float4* ap = (const float4*)g_wA + (mtile * 8) * 32 + lane;

    for (int tix = 0; tix < len; tix++) {
        asm volatile("cp.async.wait_group 1;\n" ::: "memory");   // tile tix arrived
        __syncthreads();   // also: prev iteration's obuf reads complete

        // prefetch tix+2 into the buffer freed two iterations ago
        if (tix + 2 < len) load_tile(tix + 2, (tix + 2) % 3);
        asm volatile("cp.async.commit_group;\n" ::: "memory");

        const float* tp = stage + (tix % 3) * STAGEN;
        const size_t n0 = (size_t)(base + tix) * NTILE;

        float c[4][4];
#pragma unroll
        for (int nt = 0; nt < 4; nt++)
#pragma unroll
            for (int r = 0; r < 4; r++) c[nt][r] = 0.0f;

#pragma unroll
        for (int kk = 0; kk < 8; kk++) {
            float4 av = __ldg(ap + kk * 32);
            u32 a0 = __float_as_uint(av.x), a1 = __float_as_uint(av.y);
            u32 a2 = __float_as_uint(av.z), a3 = __float_as_uint(av.w);
            const float* r0 = tp + (kk * 8 + t) * SROW + nhalf * 32 + g;
            const float* r1 = r0 + 4 * SROW;
#pragma unroll
            for (int nt = 0; nt < 4; nt++) {
                u32 b0 = f2tf32(r0[nt * 8]);
                u32 b1 = f2tf32(r1[nt * 8]);
                asm volatile(
                    "mma.sync.aligned.m16n8k8.row.col.f32.tf32.tf32.f32 "
                    "{%0,%1,%2,%3}, {%4,%5,%6,%7}, {%8,%9}, {%0,%1,%2,%3};"
                    : "+f"(c[nt][0]), "+f"(c[nt][1]), "+f"(c[nt][2]), "+f"(c[nt][3])
                    : "r"(a0), "r"(a1), "r"(a2), "r"(a3), "r"(b0), "r"(b1));
            }
        }
        __syncthreads();   // all LDS reads of stage[tix%3] + prev obuf use done

        // ---- transposed epilogue: frags -> obuf[batch][col] ----
        {
            float* ob = obuf + (mtile * 16 + g) * OROW + nhalf * 32 + t * 2;
#pragma unroll
            for (int nt = 0; nt < 4; nt++) {
                *(float2*)(ob + nt * 8)            = make_float2(c[nt][0], c[nt][1]);
                *(float2*)(ob + nt * 8 + 8 * OROW) = make_float2(c[nt][2], c[nt][3]);
            }
        }
        __syncthreads();

        // coalesced read + STG.128: thread -> 4 rows, 16B chunk each
        {
            const int c4 = (tid & 15) * 4;
            const int r0w = tid >> 4;
#pragma unroll
            for (int i = 0; i < 4; i++) {
                int r = r0w + i * 16;
                float4 v = *(float4*)(obuf + r * OROW + c4);
                *(float4*)(out + (size_t)r * NTOT + n0 + c4) = v;
            }
        }
        // loop-top __syncthreads protects obuf before next STS and stage before cp.async
    }
}

// ---------------- launcher ----------------
extern "C" void kernel_launch(void* const* d_in, const int* in_sizes, int n_in,
                              void* d_out, int out_size) {
    const float* mem = (const float*)d_in[0];
    const float* q   = (const float*)d_in[1];
    if (n_in >= 2 && in_sizes[0] < in_sizes[1]) {
        const float* t = mem; mem = q; q = t;
    }
    float* out = (float*)d_out;

    cudaFuncSetAttribute(einsum_kernel,
                         cudaFuncAttributeMaxDynamicSharedMemorySize, SMEM_BYTES);

    mean_kernel<<<M_SLOTS * CHANS / 8, 256>>>(mem);
    weights_kernel<<<BATCH, 256>>>(q);
    pack_kernel<<<1, 256>>>();
    einsum_kernel<<<GRID, 256, SMEM_BYTES>>>(mem, out);
}

// round 8
// speedup vs baseline: 2.3607x; 1.1607x over previous
#include <cuda_runtime.h>
#include <cuda_bf16.h>
#include <cstdint>

typedef unsigned int u32;

#define M_SLOTS 60
#define CHANS   256
#define HW      3136           // 56*56
#define NTOT    802816         // 256*3136 elements per memory slot
#define BATCH   64
#define KPAD    64             // K padded to 64 (rows 60..63 of W are zero)
#define EPS     1e-8f

#define NTILE   64             // spatial floats per tile
#define SROW    72             // padded stage row (72 mod 32 = 8 -> conflict-free B-frags)
#define STAGEN  (64 * SROW)    // 4608 floats per stage buffer
#define NSTAGE  4
#define SMEM_BYTES (NSTAGE * STAGEN * 4)   // 73728 B
#define NT      (NTOT / NTILE) // 12544 tiles
#define GRID    296            // 148 SMs * 2 CTAs

// Scratch (device globals — no allocation allowed)
__device__ float g_mem_avg[M_SLOTS * CHANS];   // [m][c]
__device__ float g_wbm[BATCH * KPAD];          // [b][k] tf32-rounded weights, k>=60 zero
// A fragments, warp-coalesced: [mtile(4)][kk(8)][lane(32)][r(4)]
__device__ float g_wA[4 * 8 * 32 * 4];

__device__ __forceinline__ u32 f2tf32(float x) {
    u32 r;
    asm("cvt.rna.tf32.f32 %0, %1;" : "=r"(r) : "f"(x));
    return r;
}

// ---------------- kernel 1: mean over H,W ----------------
__global__ __launch_bounds__(256) void mean_kernel(const float* __restrict__ mem) {
    const int wrp  = threadIdx.x >> 5;
    const int lane = threadIdx.x & 31;
    const int r = blockIdx.x * 8 + wrp;                       // 0..15359
    const float4* p = (const float4*)(mem + (size_t)r * HW);  // 784 float4 per row
    float s = 0.0f;
#pragma unroll 5
    for (int i = lane; i < 784; i += 32) {
        float4 v = __ldg(p + i);
        s += (v.x + v.y) + (v.z + v.w);
    }
#pragma unroll
    for (int o = 16; o > 0; o >>= 1) s += __shfl_xor_sync(0xffffffffu, s, o);
    if (lane == 0) g_mem_avg[r] = s * (1.0f / (float)HW);
}

// ---------------- kernel 2: cosine sim + softmax -> tf32 weights ----------------
__global__ void weights_kernel(const float* __restrict__ q) {
    const int b = blockIdx.x;
    const int tid = threadIdx.x;
    const int lane = tid & 31;
    const int wrp = tid >> 5;

    __shared__ float s_cos[M_SLOTS];
    __shared__ float s_qn;

    if (wrp == 0) {
        float s = 0.0f;
        const float* qr = q + b * CHANS;
        for (int i = lane; i < CHANS; i += 32) { float v = qr[i]; s += v * v; }
        for (int o = 16; o > 0; o >>= 1) s += __shfl_xor_sync(0xffffffffu, s, o);
        if (lane == 0) s_qn = sqrtf(s);
    }
    __syncthreads();
    const float qn = fmaxf(s_qn, EPS);

    for (int m = wrp; m < M_SLOTS; m += 8) {
        const float* mr = g_mem_avg + m * CHANS;
        const float* qr = q + b * CHANS;
        float dot = 0.0f, mn2 = 0.0f;
        for (int i = lane; i < CHANS; i += 32) {
            float mv = mr[i];
            dot = fmaf(mv, qr[i], dot);
            mn2 = fmaf(mv, mv, mn2);
        }
        for (int o = 16; o > 0; o >>= 1) {
            dot += __shfl_xor_sync(0xffffffffu, dot, o);
            mn2 += __shfl_xor_sync(0xffffffffu, mn2, o);
        }
        if (lane == 0) s_cos[m] = dot / (qn * fmaxf(sqrtf(mn2), EPS));
    }
    __syncthreads();

    if (wrp == 0) {
        float v0 = (lane < M_SLOTS) ? s_cos[lane] : -1e30f;
        float v1 = (lane + 32 < M_SLOTS) ? s_cos[lane + 32] : -1e30f;
        float mx = fmaxf(v0, v1);
        for (int o = 16; o > 0; o >>= 1) mx = fmaxf(mx, __shfl_xor_sync(0xffffffffu, mx, o));
        float e0 = (lane < M_SLOTS) ? expf(v0 - mx) : 0.0f;
        float e1 = (lane + 32 < M_SLOTS) ? expf(v1 - mx) : 0.0f;
        float sm = e0 + e1;
        for (int o = 16; o > 0; o >>= 1) sm += __shfl_xor_sync(0xffffffffu, sm, o);
        float inv = 1.0f / sm;
        if (lane < M_SLOTS)
            g_wbm[b * KPAD + lane] = __uint_as_float(f2tf32(e0 * inv));
        if (lane + 32 < M_SLOTS)
            g_wbm[b * KPAD + lane + 32] = __uint_as_float(f2tf32(e1 * inv));
        if (lane < KPAD - M_SLOTS)                    // zero pad k = 60..63
            g_wbm[b * KPAD + M_SLOTS + lane] = 0.0f;
    }
}

// ---------------- kernel 2b: pack A fragments ----------------
// g_wA[mtile][kk][lane][r]: warp reading (kk fixed, lane varying) is fully coalesced.
__global__ void pack_kernel() {
    const int tid = threadIdx.x;
#pragma unroll
    for (int i = 0; i < 4; i++) {
        int slot = tid + i * 256;              // 0..1023 -> (mtile, kk, lane)
        int mtile = slot >> 8;
        int kk    = (slot >> 5) & 7;
        int lane  = slot & 31;
        int g = lane >> 2, t = lane & 3;
        int m0 = mtile * 16;
        int k  = kk * 8 + t;
        float4 v;
        v.x = g_wbm[(m0 + g)     * KPAD + k];
        v.y = g_wbm[(m0 + g + 8) * KPAD + k];
        v.z = g_wbm[(m0 + g)     * KPAD + k + 4];
        v.w = g_wbm[(m0 + g + 8) * KPAD + k + 4];
        *(float4*)(g_wA + (size_t)slot * 4) = v;
    }
}

// ---------------- kernel 3: einsum, 4-stage cp.async ring, hoisted A frags ----------------
// 296 persistent CTAs, ~42 tiles each. Epilogue transposes through the just-consumed
// stage buffer (free until prefetch of tix+4). k-pad rows may hold stale (finite)
// output data after reuse — harmless: they multiply exactly-zero weight rows.
__global__ __launch_bounds__(256, 2) void einsum_kernel(const float* __restrict__ mem,
                                                        float* __restrict__ out) {
    extern __shared__ float stage[];   // NSTAGE * STAGEN

    const int tid  = threadIdx.x;
    const int lane = tid & 31;
    const int wrp  = tid >> 5;
    const int mtile = wrp & 3;
    const int nhalf = wrp >> 2;
    const int g = lane >> 2, t = lane & 3;

    const int qq = NT / GRID, rr = NT % GRID;          // 42, 112
    const int bid = blockIdx.x;
    const int len  = qq + (bid < rr ? 1 : 0);
    const int base = bid * qq + (bid < rr ? bid : rr);

    const u32 sbase = (u32)__cvta_generic_to_shared(stage);

    // zero k-pad rows 60..63 of all stage buffers (uninit smem could be NaN bits;
    // after first epilogue reuse they hold finite data, which is fine: 0 * finite = 0)
    for (int j = tid; j < NSTAGE * 4 * SROW; j += 256) {
        int s = j / (4 * SROW);
        int rem = j % (4 * SROW);
        stage[s * STAGEN + (60 + rem / SROW) * SROW + (rem % SROW)] = 0.0f;
    }

    // stage loader: 60 rows x 16 chunks of 16B = 960 chunks
    auto load_tile = [&](int tix) {
        const int bsel = tix & 3;
#pragma unroll
        for (int i = 0; i < 4; i++) {
            int j = tid + i * 256;
            if (j < 960) {
                int row = j >> 4, c = (j & 15) << 2;
                u32 dst = sbase + (u32)((bsel * STAGEN + row * SROW + c) * 4);
                const float* src = mem + (size_t)row * NTOT + (size_t)(base + tix) * NTILE + c;
                asm volatile("cp.async.cg.shared.global [%0], [%1], 16;\n"
                             :: "r"(dst), "l"(src));
            }
        }
    };

    if (0 < len) load_tile(0);
    asm volatile("cp.async.commit_group;\n" ::: "memory");
    if (1 < len) load_tile(1);
    asm volatile("cp.async.commit_group;\n" ::: "memory");
    if (2 < len) load_tile(2);
    asm volatile("cp.async.commit_group;\n" ::: "memory");

    // ---- hoisted A fragments: 8 x LDG.128, live across the whole tile loop ----
    float4 a[8];
    {
        const float4* ap = (const float4*)g_wA + (mtile * 8) * 32 + lane;
#pragma unroll
        for (int kk = 0; kk < 8; kk++) a[kk] = __ldg(ap + kk * 32);
    }

    for (int tix = 0; tix < len; tix++) {
        asm volatile("cp.async.wait_group 2;\n" ::: "memory");   // tile tix arrived
        __syncthreads();   // + prev iteration's epilogue reads of stage[(tix-1)&3] done

        if (tix + 3 < len) load_tile(tix + 3);
        asm volatile("cp.async.commit_group;\n" ::: "memory");

        float* tp = stage + (tix & 3) * STAGEN;
        const size_t n0 = (size_t)(base + tix) * NTILE;

        float c[4][4];
#pragma unroll
        for (int nt = 0; nt < 4; nt++)
#pragma unroll
            for (int r = 0; r < 4; r++) c[nt][r] = 0.0f;

#pragma unroll
        for (int kk = 0; kk < 8; kk++) {
            u32 a0 = __float_as_uint(a[kk].x), a1 = __float_as_uint(a[kk].y);
            u32 a2 = __float_as_uint(a[kk].z), a3 = __float_as_uint(a[kk].w);
            const float* r0 = tp + (kk * 8 + t) * SROW + nhalf * 32 + g;
            const float* r1 = r0 + 4 * SROW;
#pragma unroll
            for (int nt = 0; nt < 4; nt++) {
                u32 b0 = f2tf32(r0[nt * 8]);
                u32 b1 = f2tf32(r1[nt * 8]);
                asm volatile(
                    "mma.sync.aligned.m16n8k8.row.col.f32.tf32.tf32.f32 "
                    "{%0,%1,%2,%3}, {%4,%5,%6,%7}, {%8,%9}, {%0,%1,%2,%3};"
                    : "+f"(c[nt][0]), "+f"(c[nt][1]), "+f"(c[nt][2]), "+f"(c[nt][3])
                    : "r"(a0), "r"(a1), "r"(a2), "r"(a3), "r"(b0), "r"(b1));
            }
        }
        __syncthreads();   // all warps done reading stage[tix&3] -> safe to reuse as obuf

        // ---- transposed epilogue through the just-consumed stage buffer ----
        {
            float* ob = tp + (mtile * 16 + g) * SROW + nhalf * 32 + t * 2;
#pragma unroll
            for (int nt = 0; nt < 4; nt++) {
                *(float2*)(ob + nt * 8)            = make_float2(c[nt][0], c[nt][1]);
                *(float2*)(ob + nt * 8 + 8 * SROW) = make_float2(c[nt][2], c[nt][3]);
            }
        }
        __syncthreads();

        // coalesced read + STG.128: thread -> 4 batch rows, 16B chunk each
        {
            const int c4 = (tid & 15) * 4;
            const int r0w = tid >> 4;
#pragma unroll
            for (int i = 0; i < 4; i++) {
                int r = r0w + i * 16;
                float4 v = *(float4*)(tp + r * SROW + c4);
                *(float4*)(out + (size_t)r * NTOT + n0 + c4) = v;
            }
        }
        // loop-top wait+sync protects stage[tix&3] (next written by prefetch of tix+4)
    }
}

// ---------------- launcher ----------------
extern "C" void kernel_launch(void* const* d_in, const int* in_sizes, int n_in,
                              void* d_out, int out_size) {
    const float* mem = (const float*)d_in[0];
    const float* q   = (const float*)d_in[1];
    if (n_in >= 2 && in_sizes[0] < in_sizes[1]) {
        const float* t = mem; mem = q; q = t;
    }
    float* out = (float*)d_out;

    cudaFuncSetAttribute(einsum_kernel,
                         cudaFuncAttributeMaxDynamicSharedMemorySize, SMEM_BYTES);

    mean_kernel<<<M_SLOTS * CHANS / 8, 256>>>(mem);
    weights_kernel<<<BATCH, 256>>>(q);
    pack_kernel<<<1, 256>>>();
    einsum_kernel<<<GRID, 256, SMEM_BYTES>>>(mem, out);
}